// round 12
// baseline (speedup 1.0000x reference)
#include <cuda_runtime.h>
#include <math.h>

typedef unsigned int u32;
typedef unsigned long long u64;

#define HWn 65536
#define NBC 512

// Q,K,V scratch (fp32, tf32-prerounded), layout [proj][b*64+c][h*256+w]
__device__ float g_qkv[3ULL * NBC * HWn];

// ---------------- helpers ---------------------------------------------------
__device__ __forceinline__ u32 s2u(const void* p) { return (u32)__cvta_generic_to_shared(p); }
__device__ __forceinline__ u32 cvt_tf32(float f) {
    u32 r; asm("cvt.rna.tf32.f32 %0,%1;" : "=r"(r) : "f"(f)); return r;
}
__device__ __forceinline__ u32 fau(float f) { return __float_as_uint(f); }
__device__ __forceinline__ float uaf(u32 u) { return __uint_as_float(u); }
__device__ __forceinline__ void mma8(float* c, u32 a0, u32 a1, u32 a2, u32 a3,
                                     u32 b0, u32 b1) {
    asm("mma.sync.aligned.m16n8k8.row.col.f32.tf32.tf32.f32 "
        "{%0,%1,%2,%3},{%4,%5,%6,%7},{%8,%9},{%0,%1,%2,%3};"
        : "+f"(c[0]), "+f"(c[1]), "+f"(c[2]), "+f"(c[3])
        : "r"(a0), "r"(a1), "r"(a2), "r"(a3), "r"(b0), "r"(b1));
}
__device__ __forceinline__ void cpa16(u32 smem, const float* g) {
    asm volatile("cp.async.cg.shared.global [%0],[%1],16;" :: "r"(smem), "l"(g));
}
#define CPA_COMMIT() asm volatile("cp.async.commit_group;" ::: "memory")
#define CPA_WAIT0()  asm volatile("cp.async.wait_group 0;" ::: "memory")

// ---------------------------------------------------------------------------
// Kernel 1: QKV projection, persistent CTAs (byte-identical control).
// ---------------------------------------------------------------------------
#define T_PER 4
#define XRS 136
#define QW   0
#define QB   (192*68)
#define QAH  (QB + 192)
#define QAL  (QAH + 64*XRS)
#define QRAW (QAL + 64*XRS)
#define SMEM_QKV_FLOATS (QRAW + 2*64*XRS)     // 48064 -> 192,256 B

__global__ __launch_bounds__(256, 1)
void qkv_mma(const float* __restrict__ x,
             const float* __restrict__ Wq, const float* __restrict__ bq,
             const float* __restrict__ Wk, const float* __restrict__ bk,
             const float* __restrict__ Wv, const float* __restrict__ bv)
{
    extern __shared__ float sq[];
    const int tid  = threadIdx.x;
    const int lane = tid & 31;
    const int wid  = tid >> 5;
    const int lr   = lane >> 2;
    const int lc   = lane & 3;
    const int wm   = (wid & 1) * 64;
    const int wn   = (wid >> 1) * 48;

    for (int idx = tid; idx < 192 * 64; idx += 256) {
        int o = idx >> 6, k = idx & 63;
        const float* src = (o < 64) ? Wq : ((o < 128) ? Wk : Wv);
        sq[QW + o * 68 + k] = uaf(cvt_tf32(src[(o & 63) * 64 + k]));
    }
    if (tid < 192)
        sq[QB + tid] = (tid < 64) ? bq[tid] : ((tid < 128) ? bk[tid - 64] : bv[tid - 128]);

    auto issueX = [&](int j) {
        int p0  = (blockIdx.x * T_PER + j) * 128;
        int b   = p0 >> 16;
        int hw0 = p0 & 65535;
        const float* xb = x + (size_t)b * 64 * HWn + hw0;
        u32 dst = s2u(sq + QRAW + (j & 1) * 64 * XRS);
        #pragma unroll
        for (int i = 0; i < 8; i++) {
            int idx = tid + 256 * i;
            int ch = idx >> 5, seg = idx & 31;
            cpa16(dst + (u32)(ch * XRS + seg * 4) * 4, xb + (size_t)ch * HWn + seg * 4);
        }
    };

    issueX(0); CPA_COMMIT();

    for (int j = 0; j < T_PER; j++) {
        CPA_WAIT0();
        __syncthreads();
        if (j + 1 < T_PER) { issueX(j + 1); CPA_COMMIT(); }

        {
            const float* raw = sq + QRAW + (j & 1) * 64 * XRS;
            #pragma unroll
            for (int i = 0; i < 8; i++) {
                int idx = tid + 256 * i;
                int ch = idx >> 5, seg = idx & 31;
                float4 v = *(const float4*)(raw + ch * XRS + seg * 4);
                float4 h, l;
                h.x = uaf(cvt_tf32(v.x)); l.x = uaf(cvt_tf32(v.x - h.x));
                h.y = uaf(cvt_tf32(v.y)); l.y = uaf(cvt_tf32(v.y - h.y));
                h.z = uaf(cvt_tf32(v.z)); l.z = uaf(cvt_tf32(v.z - h.z));
                h.w = uaf(cvt_tf32(v.w)); l.w = uaf(cvt_tf32(v.w - h.w));
                *(float4*)(sq + QAH + ch * XRS + seg * 4) = h;
                *(float4*)(sq + QAL + ch * XRS + seg * 4) = l;
            }
        }
        __syncthreads();

        float acc[4][6][4];
        #pragma unroll
        for (int i = 0; i < 4; i++)
            #pragma unroll
            for (int jj = 0; jj < 6; jj++)
                #pragma unroll
                for (int q = 0; q < 4; q++) acc[i][jj][q] = 0.f;

        #pragma unroll 2
        for (int kk = 0; kk < 8; kk++) {
            const int kb = kk * 8;
            u32 ah[4][4], al[4][4];
            #pragma unroll
            for (int ms = 0; ms < 4; ms++) {
                int r = wm + ms * 16 + lr;
                const float* ph = sq + QAH + (kb + lc) * XRS + r;
                const float* pl = sq + QAL + (kb + lc) * XRS + r;
                ah[ms][0] = fau(ph[0]); ah[ms][1] = fau(ph[8]);
                ah[ms][2] = fau(ph[4 * XRS]); ah[ms][3] = fau(ph[4 * XRS + 8]);
                al[ms][0] = fau(pl[0]); al[ms][1] = fau(pl[8]);
                al[ms][2] = fau(pl[4 * XRS]); al[ms][3] = fau(pl[4 * XRS + 8]);
            }
            #pragma unroll
            for (int ns = 0; ns < 6; ns++) {
                const float* wp = sq + QW + (wn + ns * 8 + lr) * 68 + kb + lc;
                u32 b0 = fau(wp[0]), b1 = fau(wp[4]);
                #pragma unroll
                for (int ms = 0; ms < 4; ms++) {
                    mma8(acc[ms][ns], ah[ms][0], ah[ms][1], ah[ms][2], ah[ms][3], b0, b1);
                    mma8(acc[ms][ns], al[ms][0], al[ms][1], al[ms][2], al[ms][3], b0, b1);
                }
            }
        }

        int p0  = (blockIdx.x * T_PER + j) * 128;
        int b   = p0 >> 16;
        int hw0 = p0 & 65535;
        #pragma unroll
        for (int ms = 0; ms < 4; ms++) {
            int r0 = wm + ms * 16 + lr;
            #pragma unroll
            for (int ns = 0; ns < 6; ns++) {
                int n0 = wn + ns * 8 + 2 * lc;
                #pragma unroll
                for (int q = 0; q < 4; q++) {
                    int o = n0 + (q & 1);
                    int r = r0 + (q >> 1) * 8;
                    float v = acc[ms][ns][q] + sq[QB + o];
                    int proj = o >> 6;
                    if (proj == 0) v *= 0.25f;
                    g_qkv[((size_t)proj * NBC + (size_t)(b * 64 + (o & 63))) * HWn + hw0 + r]
                        = uaf(cvt_tf32(v));
                }
            }
        }
    }
}

// ---------------------------------------------------------------------------
// Kernel 2: attention, 512 threads (16 warps as 4m x 4n, warp tile 32x64).
// Phase A/C cp.async double-buffered; Phase C reads V natural layout.
// ---------------------------------------------------------------------------
#define PS_STRIDE 260
#define AB_STRIDE 36
#define AB_FLOATS (128*AB_STRIDE + 256*AB_STRIDE)   // 13824 per buffer (in Ps)
#define VS_STRIDE 260
#define VB_FLOATS (32 * VS_STRIDE)                   // 8320 per buffer
#define PS_FLOATS  (128 * PS_STRIDE)                 // 33280 (>= 2*13824)
#define OFF_VS     PS_FLOATS
#define OFF_RED    (OFF_VS + 2 * VB_FLOATS)          // 49920
#define OFF_ROWSC  (OFF_RED + 512)
#define SMEM_ATTN_FLOATS (OFF_ROWSC + 128)           // 50560 -> 202,240 B

__global__ __launch_bounds__(512, 1)
void attn_kernel(const float* __restrict__ gamma, const float* __restrict__ beta,
                 const float* __restrict__ rmean, const float* __restrict__ rvar,
                 const float* __restrict__ alphap, float* __restrict__ out)
{
    extern __shared__ float sm[];
    float* Ps    = sm;                      // 128 x 260 (aliases phase-A bufs)
    float* Vs    = sm + OFF_VS;             // 2 x 32 x 260 (natural V chunks)
    float* reds  = sm + OFF_RED;
    float* rowsc = sm + OFF_ROWSC;

    const int tid  = threadIdx.x;
    const int lane = tid & 31;
    const int wid  = tid >> 5;              // 0..15
    const int wm   = (wid & 3) * 32;        // 4 m-warps
    const int wn   = (wid >> 2) * 64;       // 4 n-warps
    const int lr   = lane >> 2;
    const int lc   = lane & 3;

    const int bc = blockIdx.x >> 1;
    const int h0 = (blockIdx.x & 1) * 128;
    const int c  = bc & 63;

    const float* Qg = g_qkv + (size_t)bc * HWn + (size_t)h0 * 256;
    const float* Kg = g_qkv + (size_t)(NBC + bc) * HWn;
    const float* Vg = g_qkv + (size_t)(2 * NBC + bc) * HWn;

    float acc[2][8][4];
    #pragma unroll
    for (int i = 0; i < 2; i++)
        #pragma unroll
        for (int j = 0; j < 8; j++)
            #pragma unroll
            for (int k = 0; k < 4; k++) acc[i][j][k] = 0.f;

    // ===== Phase A: S = Q . K^T, k=256 in 8 cp.async-pipelined chunks of 32 =
    auto issueA = [&](int kc) {
        u32 d = s2u(sm + (kc & 1) * AB_FLOATS);
        const float* sq2 = Qg + kc * 32;
        const float* sk2 = Kg + kc * 32;
        #pragma unroll
        for (int i = 0; i < 6; i++) {
            int idx = tid + 512 * i;
            if (idx < 1024) {
                int r = idx >> 3, seg = idx & 7;
                cpa16(d + (u32)(r * AB_STRIDE + seg * 4) * 4, sq2 + (size_t)r * 256 + seg * 4);
            } else {
                int i2 = idx - 1024;
                int r = i2 >> 3, seg = i2 & 7;
                cpa16(d + (u32)(128 * AB_STRIDE + r * AB_STRIDE + seg * 4) * 4,
                      sk2 + (size_t)r * 256 + seg * 4);
            }
        }
    };
    // Phase C V chunk issue: 32 g-rows x 256 w, natural layout, stride 260
    auto issueV = [&](int gc) {
        u32 d = s2u(Vs + (gc & 1) * VB_FLOATS);
        const float* sv = Vg + (size_t)gc * 32 * 256;
        #pragma unroll
        for (int i = 0; i < 4; i++) {
            int idx = tid + 512 * i;
            int r = idx >> 6, seg = idx & 63;
            cpa16(d + (u32)(r * VS_STRIDE + seg * 4) * 4, sv + (size_t)r * 256 + seg * 4);
        }
    };

    issueA(0); CPA_COMMIT();
    for (int kc = 0; kc < 8; kc++) {
        CPA_WAIT0();
        __syncthreads();
        if (kc + 1 < 8) { issueA(kc + 1); CPA_COMMIT(); }
        const float* bufQ = sm + (kc & 1) * AB_FLOATS;
        const float* bufK = bufQ + 128 * AB_STRIDE;
        #pragma unroll
        for (int kk = 0; kk < 4; kk++) {
            const int kb = kk * 8;
            u32 af[2][4];
            #pragma unroll
            for (int ms = 0; ms < 2; ms++) {
                const float* q = bufQ + (wm + ms * 16 + lr) * AB_STRIDE + kb + lc;
                af[ms][0] = fau(q[0]);
                af[ms][1] = fau(q[8 * AB_STRIDE]);
                af[ms][2] = fau(q[4]);
                af[ms][3] = fau(q[8 * AB_STRIDE + 4]);
            }
            #pragma unroll
            for (int ns = 0; ns < 8; ns++) {
                const float* kp = bufK + (wn + ns * 8 + lr) * AB_STRIDE + kb + lc;
                u32 b0 = fau(kp[0]);
                u32 b1 = fau(kp[4]);
                #pragma unroll
                for (int ms = 0; ms < 2; ms++)
                    mma8(acc[ms][ns], af[ms][0], af[ms][1], af[ms][2], af[ms][3], b0, b1);
            }
        }
    }

    // Early-issue first V chunk: loads overlap the softmax below.
    issueV(0); CPA_COMMIT();

    // ===== Phase B: softmax over n (no max-sub; |S| <~ 8) ==================
    __syncthreads();   // all Phase A fragment reads done before Ps overwrite
    #pragma unroll
    for (int ms = 0; ms < 2; ms++)
        #pragma unroll
        for (int half = 0; half < 2; half++) {
            int row = wm + ms * 16 + lr + half * 8;
            float s = 0.f;
            #pragma unroll
            for (int ns = 0; ns < 8; ns++) {
                float e0 = __expf(acc[ms][ns][half * 2]);
                float e1 = __expf(acc[ms][ns][half * 2 + 1]);
                s += e0 + e1;
                *(float2*)(Ps + row * PS_STRIDE + wn + ns * 8 + 2 * lc) =
                    make_float2(uaf(cvt_tf32(e0)), uaf(cvt_tf32(e1)));
            }
            s += __shfl_xor_sync(0xffffffffu, s, 1);
            s += __shfl_xor_sync(0xffffffffu, s, 2);
            if (lc == 0) reds[row * 4 + (wid >> 2)] = s;
        }
    __syncthreads();
    if (tid < 128)
        rowsc[tid] = 1.f / (reds[tid * 4] + reds[tid * 4 + 1] + reds[tid * 4 + 2] + reds[tid * 4 + 3]);

    // ===== Phase C: out = P . V, k=256 g in 8 pipelined chunks of 32 =======
    #pragma unroll
    for (int i = 0; i < 2; i++)
        #pragma unroll
        for (int j = 0; j < 8; j++)
            #pragma unroll
            for (int k = 0; k < 4; k++) acc[i][j][k] = 0.f;

    for (int gc = 0; gc < 8; gc++) {
        CPA_WAIT0();
        __syncthreads();
        if (gc + 1 < 8) { issueV(gc + 1); CPA_COMMIT(); }
        const float* bufV = Vs + (gc & 1) * VB_FLOATS;
        #pragma unroll
        for (int kk = 0; kk < 4; kk++) {
            const int kb = kk * 8;
            u32 af[2][4];
            #pragma unroll
            for (int ms = 0; ms < 2; ms++) {
                const float* p = Ps + (wm + ms * 16 + lr) * PS_STRIDE + gc * 32 + kb + lc;
                af[ms][0] = fau(p[0]);
                af[ms][1] = fau(p[8 * PS_STRIDE]);
                af[ms][2] = fau(p[4]);
                af[ms][3] = fau(p[8 * PS_STRIDE + 4]);
            }
            #pragma unroll
            for (int ns = 0; ns < 8; ns++) {
                // B fragment straight from natural V: VT[n][k] == Vs[k][n]
                const float* vb = bufV + (kb + lc) * VS_STRIDE + wn + ns * 8 + lr;
                u32 b0 = fau(vb[0]);
                u32 b1 = fau(vb[4 * VS_STRIDE]);
                #pragma unroll
                for (int ms = 0; ms < 2; ms++)
                    mma8(acc[ms][ns], af[ms][0], af[ms][1], af[ms][2], af[ms][3], b0, b1);
            }
        }
    }

    // ===== Epilogue: 1/sum, BN(eval), PReLU, store =========================
    const float inv = gamma[c] * rsqrtf(rvar[c] + 1e-5f);
    const float sh  = beta[c] - rmean[c] * inv;
    const float al  = alphap[0];
    #pragma unroll
    for (int ms = 0; ms < 2; ms++)
        #pragma unroll
        for (int half = 0; half < 2; half++) {
            int row = wm + ms * 16 + lr + half * 8;
            float rs = rowsc[row] * inv;
            float* op = out + (size_t)bc * HWn + (size_t)(h0 + row) * 256;
            #pragma unroll
            for (int ns = 0; ns < 8; ns++) {
                float v0 = acc[ms][ns][half * 2]     * rs + sh;
                float v1 = acc[ms][ns][half * 2 + 1] * rs + sh;
                v0 = (v0 >= 0.f) ? v0 : al * v0;
                v1 = (v1 >= 0.f) ? v1 : al * v1;
                *(float2*)(op + wn + ns * 8 + 2 * lc) = make_float2(v0, v1);
            }
        }
}

// ---------------------------------------------------------------------------
extern "C" void kernel_launch(void* const* d_in, const int* in_sizes, int n_in,
                              void* d_out, int out_size)
{
    (void)in_sizes; (void)n_in; (void)out_size;
    const float* x     = (const float*)d_in[0];
    const float* Wq    = (const float*)d_in[1];
    const float* bq    = (const float*)d_in[2];
    const float* Wk    = (const float*)d_in[3];
    const float* bk    = (const float*)d_in[4];
    const float* Wv    = (const float*)d_in[5];
    const float* bv    = (const float*)d_in[6];
    const float* gamma = (const float*)d_in[7];
    const float* beta  = (const float*)d_in[8];
    const float* rmean = (const float*)d_in[9];
    const float* rvar  = (const float*)d_in[10];
    const float* alpha = (const float*)d_in[11];
    float* out = (float*)d_out;

    const int smem1 = SMEM_QKV_FLOATS * sizeof(float);    // 192,256 B
    const int smem2 = SMEM_ATTN_FLOATS * sizeof(float);   // 202,240 B
    cudaFuncSetAttribute(qkv_mma,     cudaFuncAttributeMaxDynamicSharedMemorySize, smem1);
    cudaFuncSetAttribute(attn_kernel, cudaFuncAttributeMaxDynamicSharedMemorySize, smem2);

    qkv_mma<<<1024, 256, smem1>>>(x, Wq, bq, Wk, bk, Wv, bv);
    attn_kernel<<<NBC * 2, 512, smem2>>>(gamma, beta, rmean, rvar, alpha, out);
}

// round 13
// speedup vs baseline: 1.0585x; 1.0585x over previous
#include <cuda_runtime.h>
#include <math.h>

typedef unsigned int u32;
typedef unsigned long long u64;

#define HWn 65536
#define NBC 512

// Q,K,V scratch (fp32, tf32-prerounded), layout [proj][b*64+c][h*256+w]
__device__ float g_qkv[3ULL * NBC * HWn];

// ---------------- helpers ---------------------------------------------------
__device__ __forceinline__ u32 s2u(const void* p) { return (u32)__cvta_generic_to_shared(p); }
__device__ __forceinline__ u32 cvt_tf32(float f) {
    u32 r; asm("cvt.rna.tf32.f32 %0,%1;" : "=r"(r) : "f"(f)); return r;
}
__device__ __forceinline__ u32 fau(float f) { return __float_as_uint(f); }
__device__ __forceinline__ float uaf(u32 u) { return __uint_as_float(u); }
__device__ __forceinline__ void mma8(float* c, u32 a0, u32 a1, u32 a2, u32 a3,
                                     u32 b0, u32 b1) {
    asm("mma.sync.aligned.m16n8k8.row.col.f32.tf32.tf32.f32 "
        "{%0,%1,%2,%3},{%4,%5,%6,%7},{%8,%9},{%0,%1,%2,%3};"
        : "+f"(c[0]), "+f"(c[1]), "+f"(c[2]), "+f"(c[3])
        : "r"(a0), "r"(a1), "r"(a2), "r"(a3), "r"(b0), "r"(b1));
}
__device__ __forceinline__ void cpa16(u32 smem, const float* g) {
    asm volatile("cp.async.cg.shared.global [%0],[%1],16;" :: "r"(smem), "l"(g));
}
#define CPA_COMMIT() asm volatile("cp.async.commit_group;" ::: "memory")
#define CPA_WAIT0()  asm volatile("cp.async.wait_group 0;" ::: "memory")

// ---------------------------------------------------------------------------
// Kernel 1: QKV projection, persistent CTAs (byte-identical control).
// ---------------------------------------------------------------------------
#define T_PER 4
#define XRS 136
#define QW   0
#define QB   (192*68)
#define QAH  (QB + 192)
#define QAL  (QAH + 64*XRS)
#define QRAW (QAL + 64*XRS)
#define SMEM_QKV_FLOATS (QRAW + 2*64*XRS)     // 48064 -> 192,256 B

__global__ __launch_bounds__(256, 1)
void qkv_mma(const float* __restrict__ x,
             const float* __restrict__ Wq, const float* __restrict__ bq,
             const float* __restrict__ Wk, const float* __restrict__ bk,
             const float* __restrict__ Wv, const float* __restrict__ bv)
{
    extern __shared__ float sq[];
    const int tid  = threadIdx.x;
    const int lane = tid & 31;
    const int wid  = tid >> 5;
    const int lr   = lane >> 2;
    const int lc   = lane & 3;
    const int wm   = (wid & 1) * 64;
    const int wn   = (wid >> 1) * 48;

    for (int idx = tid; idx < 192 * 64; idx += 256) {
        int o = idx >> 6, k = idx & 63;
        const float* src = (o < 64) ? Wq : ((o < 128) ? Wk : Wv);
        sq[QW + o * 68 + k] = uaf(cvt_tf32(src[(o & 63) * 64 + k]));
    }
    if (tid < 192)
        sq[QB + tid] = (tid < 64) ? bq[tid] : ((tid < 128) ? bk[tid - 64] : bv[tid - 128]);

    auto issueX = [&](int j) {
        int p0  = (blockIdx.x * T_PER + j) * 128;
        int b   = p0 >> 16;
        int hw0 = p0 & 65535;
        const float* xb = x + (size_t)b * 64 * HWn + hw0;
        u32 dst = s2u(sq + QRAW + (j & 1) * 64 * XRS);
        #pragma unroll
        for (int i = 0; i < 8; i++) {
            int idx = tid + 256 * i;
            int ch = idx >> 5, seg = idx & 31;
            cpa16(dst + (u32)(ch * XRS + seg * 4) * 4, xb + (size_t)ch * HWn + seg * 4);
        }
    };

    issueX(0); CPA_COMMIT();

    for (int j = 0; j < T_PER; j++) {
        CPA_WAIT0();
        __syncthreads();
        if (j + 1 < T_PER) { issueX(j + 1); CPA_COMMIT(); }

        {
            const float* raw = sq + QRAW + (j & 1) * 64 * XRS;
            #pragma unroll
            for (int i = 0; i < 8; i++) {
                int idx = tid + 256 * i;
                int ch = idx >> 5, seg = idx & 31;
                float4 v = *(const float4*)(raw + ch * XRS + seg * 4);
                float4 h, l;
                h.x = uaf(cvt_tf32(v.x)); l.x = uaf(cvt_tf32(v.x - h.x));
                h.y = uaf(cvt_tf32(v.y)); l.y = uaf(cvt_tf32(v.y - h.y));
                h.z = uaf(cvt_tf32(v.z)); l.z = uaf(cvt_tf32(v.z - h.z));
                h.w = uaf(cvt_tf32(v.w)); l.w = uaf(cvt_tf32(v.w - h.w));
                *(float4*)(sq + QAH + ch * XRS + seg * 4) = h;
                *(float4*)(sq + QAL + ch * XRS + seg * 4) = l;
            }
        }
        __syncthreads();

        float acc[4][6][4];
        #pragma unroll
        for (int i = 0; i < 4; i++)
            #pragma unroll
            for (int jj = 0; jj < 6; jj++)
                #pragma unroll
                for (int q = 0; q < 4; q++) acc[i][jj][q] = 0.f;

        #pragma unroll 2
        for (int kk = 0; kk < 8; kk++) {
            const int kb = kk * 8;
            u32 ah[4][4], al[4][4];
            #pragma unroll
            for (int ms = 0; ms < 4; ms++) {
                int r = wm + ms * 16 + lr;
                const float* ph = sq + QAH + (kb + lc) * XRS + r;
                const float* pl = sq + QAL + (kb + lc) * XRS + r;
                ah[ms][0] = fau(ph[0]); ah[ms][1] = fau(ph[8]);
                ah[ms][2] = fau(ph[4 * XRS]); ah[ms][3] = fau(ph[4 * XRS + 8]);
                al[ms][0] = fau(pl[0]); al[ms][1] = fau(pl[8]);
                al[ms][2] = fau(pl[4 * XRS]); al[ms][3] = fau(pl[4 * XRS + 8]);
            }
            #pragma unroll
            for (int ns = 0; ns < 6; ns++) {
                const float* wp = sq + QW + (wn + ns * 8 + lr) * 68 + kb + lc;
                u32 b0 = fau(wp[0]), b1 = fau(wp[4]);
                #pragma unroll
                for (int ms = 0; ms < 4; ms++) {
                    mma8(acc[ms][ns], ah[ms][0], ah[ms][1], ah[ms][2], ah[ms][3], b0, b1);
                    mma8(acc[ms][ns], al[ms][0], al[ms][1], al[ms][2], al[ms][3], b0, b1);
                }
            }
        }

        int p0  = (blockIdx.x * T_PER + j) * 128;
        int b   = p0 >> 16;
        int hw0 = p0 & 65535;
        #pragma unroll
        for (int ms = 0; ms < 4; ms++) {
            int r0 = wm + ms * 16 + lr;
            #pragma unroll
            for (int ns = 0; ns < 6; ns++) {
                int n0 = wn + ns * 8 + 2 * lc;
                #pragma unroll
                for (int q = 0; q < 4; q++) {
                    int o = n0 + (q & 1);
                    int r = r0 + (q >> 1) * 8;
                    float v = acc[ms][ns][q] + sq[QB + o];
                    int proj = o >> 6;
                    if (proj == 0) v *= 0.25f;
                    g_qkv[((size_t)proj * NBC + (size_t)(b * 64 + (o & 63))) * HWn + hw0 + r]
                        = uaf(cvt_tf32(v));
                }
            }
        }
    }
}

// ---------------------------------------------------------------------------
// Kernel 2: attention, 256 threads (8 warps as 2m x 4n, warp tile 64x64 —
// the LDS-minimal geometry). Phase A chunk=64 (4 chunks, half the barriers);
// Phase C reads V natural layout, 8 chunks of 32.
// ---------------------------------------------------------------------------
#define PS_STRIDE 260
#define A64S 68
#define A64_BUF (384 * A64S)                 // 26112 floats per buffer
#define VS_STRIDE 260
#define VB_FLOATS (32 * VS_STRIDE)           // 8320 per buffer
#define PS_FLOATS  (128 * PS_STRIDE)         // 33280
#define OFF_VS     PS_FLOATS                 // V bufs [33280, 49920)
#define OFF_RED    (2 * A64_BUF)             // 52224 (beyond A-buffer span)
#define OFF_ROWSC  (OFF_RED + 512)
#define SMEM_ATTN_FLOATS (OFF_ROWSC + 128)   // 52864 -> 211,456 B

__global__ __launch_bounds__(256, 1)
void attn_kernel(const float* __restrict__ gamma, const float* __restrict__ beta,
                 const float* __restrict__ rmean, const float* __restrict__ rvar,
                 const float* __restrict__ alphap, float* __restrict__ out)
{
    extern __shared__ float sm[];
    float* Ps    = sm;                      // 128 x 260 (aliases A-buffer 0)
    float* Vs    = sm + OFF_VS;             // 2 x 32 x 260 (aliases A-buffer 1)
    float* reds  = sm + OFF_RED;
    float* rowsc = sm + OFF_ROWSC;

    const int tid  = threadIdx.x;
    const int lane = tid & 31;
    const int wid  = tid >> 5;
    const int wm   = (wid & 1) * 64;
    const int wn   = (wid >> 1) * 64;
    const int lr   = lane >> 2;
    const int lc   = lane & 3;

    const int bc = blockIdx.x >> 1;
    const int h0 = (blockIdx.x & 1) * 128;
    const int c  = bc & 63;

    const float* Qg = g_qkv + (size_t)bc * HWn + (size_t)h0 * 256;
    const float* Kg = g_qkv + (size_t)(NBC + bc) * HWn;
    const float* Vg = g_qkv + (size_t)(2 * NBC + bc) * HWn;

    float acc[4][8][4];
    #pragma unroll
    for (int i = 0; i < 4; i++)
        #pragma unroll
        for (int j = 0; j < 8; j++)
            #pragma unroll
            for (int k = 0; k < 4; k++) acc[i][j][k] = 0.f;

    // ===== Phase A: S = Q . K^T, k=256 in 4 cp.async-pipelined chunks of 64 =
    auto issueA = [&](int kc) {
        u32 d = s2u(sm + (kc & 1) * A64_BUF);
        const float* sq2 = Qg + kc * 64;
        const float* sk2 = Kg + kc * 64;
        #pragma unroll
        for (int i = 0; i < 24; i++) {
            int idx = tid + 256 * i;
            if (idx < 2048) {                       // Q: 128 rows x 16 float4
                int r = idx >> 4, seg = idx & 15;
                cpa16(d + (u32)(r * A64S + seg * 4) * 4, sq2 + (size_t)r * 256 + seg * 4);
            } else {                                // K: 256 rows x 16 float4
                int i2 = idx - 2048;
                int r = i2 >> 4, seg = i2 & 15;
                cpa16(d + (u32)(128 * A64S + r * A64S + seg * 4) * 4,
                      sk2 + (size_t)r * 256 + seg * 4);
            }
        }
    };
    // Phase C V chunk issue: 32 g-rows x 256 w, natural layout, stride 260
    auto issueV = [&](int gc) {
        u32 d = s2u(Vs + (gc & 1) * VB_FLOATS);
        const float* sv = Vg + (size_t)gc * 32 * 256;
        #pragma unroll
        for (int i = 0; i < 8; i++) {
            int idx = tid + 256 * i;
            int r = idx >> 6, seg = idx & 63;
            cpa16(d + (u32)(r * VS_STRIDE + seg * 4) * 4, sv + (size_t)r * 256 + seg * 4);
        }
    };

    issueA(0); CPA_COMMIT();
    for (int kc = 0; kc < 4; kc++) {
        CPA_WAIT0();
        __syncthreads();
        if (kc + 1 < 4) { issueA(kc + 1); CPA_COMMIT(); }
        const float* bufQ = sm + (kc & 1) * A64_BUF;
        const float* bufK = bufQ + 128 * A64S;
        #pragma unroll 2
        for (int kk = 0; kk < 8; kk++) {
            const int kb = kk * 8;
            u32 af[4][4];
            #pragma unroll
            for (int ms = 0; ms < 4; ms++) {
                const float* q = bufQ + (wm + ms * 16 + lr) * A64S + kb + lc;
                af[ms][0] = fau(q[0]);
                af[ms][1] = fau(q[8 * A64S]);
                af[ms][2] = fau(q[4]);
                af[ms][3] = fau(q[8 * A64S + 4]);
            }
            #pragma unroll
            for (int ns = 0; ns < 8; ns++) {
                const float* kp = bufK + (wn + ns * 8 + lr) * A64S + kb + lc;
                u32 b0 = fau(kp[0]);
                u32 b1 = fau(kp[4]);
                #pragma unroll
                for (int ms = 0; ms < 4; ms++)
                    mma8(acc[ms][ns], af[ms][0], af[ms][1], af[ms][2], af[ms][3], b0, b1);
            }
        }
    }

    // All Phase A buffer reads complete before V cp.asyncs land in the
    // aliased buffer-1 region and before Ps overwrites buffer 0.
    __syncthreads();
    issueV(0); CPA_COMMIT();

    // ===== Phase B: softmax over n (no max-sub; |S| <~ 8) ==================
    #pragma unroll
    for (int ms = 0; ms < 4; ms++)
        #pragma unroll
        for (int half = 0; half < 2; half++) {
            int row = wm + ms * 16 + lr + half * 8;
            float s = 0.f;
            #pragma unroll
            for (int ns = 0; ns < 8; ns++) {
                float e0 = __expf(acc[ms][ns][half * 2]);
                float e1 = __expf(acc[ms][ns][half * 2 + 1]);
                s += e0 + e1;
                *(float2*)(Ps + row * PS_STRIDE + wn + ns * 8 + 2 * lc) =
                    make_float2(uaf(cvt_tf32(e0)), uaf(cvt_tf32(e1)));
            }
            s += __shfl_xor_sync(0xffffffffu, s, 1);
            s += __shfl_xor_sync(0xffffffffu, s, 2);
            if (lc == 0) reds[row * 4 + (wid >> 1)] = s;
        }
    __syncthreads();
    if (tid < 128)
        rowsc[tid] = 1.f / (reds[tid * 4] + reds[tid * 4 + 1] + reds[tid * 4 + 2] + reds[tid * 4 + 3]);

    // ===== Phase C: out = P . V, k=256 g in 8 pipelined chunks of 32 =======
    #pragma unroll
    for (int i = 0; i < 4; i++)
        #pragma unroll
        for (int j = 0; j < 8; j++)
            #pragma unroll
            for (int k = 0; k < 4; k++) acc[i][j][k] = 0.f;

    for (int gc = 0; gc < 8; gc++) {
        CPA_WAIT0();
        __syncthreads();
        if (gc + 1 < 8) { issueV(gc + 1); CPA_COMMIT(); }
        const float* bufV = Vs + (gc & 1) * VB_FLOATS;
        #pragma unroll
        for (int kk = 0; kk < 4; kk++) {
            const int kb = kk * 8;
            u32 af[4][4];
            #pragma unroll
            for (int ms = 0; ms < 4; ms++) {
                const float* p = Ps + (wm + ms * 16 + lr) * PS_STRIDE + gc * 32 + kb + lc;
                af[ms][0] = fau(p[0]);
                af[ms][1] = fau(p[8 * PS_STRIDE]);
                af[ms][2] = fau(p[4]);
                af[ms][3] = fau(p[8 * PS_STRIDE + 4]);
            }
            #pragma unroll
            for (int ns = 0; ns < 8; ns++) {
                // B fragment straight from natural V: VT[n][k] == Vs[k][n]
                const float* vb = bufV + (kb + lc) * VS_STRIDE + wn + ns * 8 + lr;
                u32 b0 = fau(vb[0]);
                u32 b1 = fau(vb[4 * VS_STRIDE]);
                #pragma unroll
                for (int ms = 0; ms < 4; ms++)
                    mma8(acc[ms][ns], af[ms][0], af[ms][1], af[ms][2], af[ms][3], b0, b1);
            }
        }
    }

    // ===== Epilogue: 1/sum, BN(eval), PReLU, store =========================
    const float inv = gamma[c] * rsqrtf(rvar[c] + 1e-5f);
    const float sh  = beta[c] - rmean[c] * inv;
    const float al  = alphap[0];
    #pragma unroll
    for (int ms = 0; ms < 4; ms++)
        #pragma unroll
        for (int half = 0; half < 2; half++) {
            int row = wm + ms * 16 + lr + half * 8;
            float rs = rowsc[row] * inv;
            float* op = out + (size_t)bc * HWn + (size_t)(h0 + row) * 256;
            #pragma unroll
            for (int ns = 0; ns < 8; ns++) {
                float v0 = acc[ms][ns][half * 2]     * rs + sh;
                float v1 = acc[ms][ns][half * 2 + 1] * rs + sh;
                v0 = (v0 >= 0.f) ? v0 : al * v0;
                v1 = (v1 >= 0.f) ? v1 : al * v1;
                *(float2*)(op + wn + ns * 8 + 2 * lc) = make_float2(v0, v1);
            }
        }
}

// ---------------------------------------------------------------------------
extern "C" void kernel_launch(void* const* d_in, const int* in_sizes, int n_in,
                              void* d_out, int out_size)
{
    (void)in_sizes; (void)n_in; (void)out_size;
    const float* x     = (const float*)d_in[0];
    const float* Wq    = (const float*)d_in[1];
    const float* bq    = (const float*)d_in[2];
    const float* Wk    = (const float*)d_in[3];
    const float* bk    = (const float*)d_in[4];
    const float* Wv    = (const float*)d_in[5];
    const float* bv    = (const float*)d_in[6];
    const float* gamma = (const float*)d_in[7];
    const float* beta  = (const float*)d_in[8];
    const float* rmean = (const float*)d_in[9];
    const float* rvar  = (const float*)d_in[10];
    const float* alpha = (const float*)d_in[11];
    float* out = (float*)d_out;

    const int smem1 = SMEM_QKV_FLOATS * sizeof(float);    // 192,256 B
    const int smem2 = SMEM_ATTN_FLOATS * sizeof(float);   // 211,456 B
    cudaFuncSetAttribute(qkv_mma,     cudaFuncAttributeMaxDynamicSharedMemorySize, smem1);
    cudaFuncSetAttribute(attn_kernel, cudaFuncAttributeMaxDynamicSharedMemorySize, smem2);

    qkv_mma<<<1024, 256, smem1>>>(x, Wq, bq, Wk, bk, Wv, bv);
    attn_kernel<<<NBC * 2, 256, smem2>>>(gamma, beta, rmean, rvar, alpha, out);
}

// round 14
// speedup vs baseline: 1.0591x; 1.0006x over previous
#include <cuda_runtime.h>
#include <math.h>

typedef unsigned int u32;
typedef unsigned long long u64;

#define HWn 65536
#define NBC 512

// Q,K,V scratch (fp32, tf32-prerounded), layout [proj][b*64+c][h*256+w]
__device__ float g_qkv[3ULL * NBC * HWn];

// ---------------- helpers ---------------------------------------------------
__device__ __forceinline__ u32 s2u(const void* p) { return (u32)__cvta_generic_to_shared(p); }
__device__ __forceinline__ u32 cvt_tf32(float f) {
    u32 r; asm("cvt.rna.tf32.f32 %0,%1;" : "=r"(r) : "f"(f)); return r;
}
__device__ __forceinline__ u32 fau(float f) { return __float_as_uint(f); }
__device__ __forceinline__ float uaf(u32 u) { return __uint_as_float(u); }
__device__ __forceinline__ void mma8(float* c, u32 a0, u32 a1, u32 a2, u32 a3,
                                     u32 b0, u32 b1) {
    asm("mma.sync.aligned.m16n8k8.row.col.f32.tf32.tf32.f32 "
        "{%0,%1,%2,%3},{%4,%5,%6,%7},{%8,%9},{%0,%1,%2,%3};"
        : "+f"(c[0]), "+f"(c[1]), "+f"(c[2]), "+f"(c[3])
        : "r"(a0), "r"(a1), "r"(a2), "r"(a3), "r"(b0), "r"(b1));
}
__device__ __forceinline__ void cpa16(u32 smem, const float* g) {
    asm volatile("cp.async.cg.shared.global [%0],[%1],16;" :: "r"(smem), "l"(g));
}
#define CPA_COMMIT() asm volatile("cp.async.commit_group;" ::: "memory")
#define CPA_WAIT0()  asm volatile("cp.async.wait_group 0;" ::: "memory")

// ---------------------------------------------------------------------------
// Kernel 1: QKV projection, persistent CTAs. Mainloop kk fully unrolled so
// ptxas can pipeline fragment loads across k-steps.
// ---------------------------------------------------------------------------
#define T_PER 4
#define XRS 136
#define QW   0
#define QB   (192*68)
#define QAH  (QB + 192)
#define QAL  (QAH + 64*XRS)
#define QRAW (QAL + 64*XRS)
#define SMEM_QKV_FLOATS (QRAW + 2*64*XRS)     // 48064 -> 192,256 B

__global__ __launch_bounds__(256, 1)
void qkv_mma(const float* __restrict__ x,
             const float* __restrict__ Wq, const float* __restrict__ bq,
             const float* __restrict__ Wk, const float* __restrict__ bk,
             const float* __restrict__ Wv, const float* __restrict__ bv)
{
    extern __shared__ float sq[];
    const int tid  = threadIdx.x;
    const int lane = tid & 31;
    const int wid  = tid >> 5;
    const int lr   = lane >> 2;
    const int lc   = lane & 3;
    const int wm   = (wid & 1) * 64;
    const int wn   = (wid >> 1) * 48;

    for (int idx = tid; idx < 192 * 64; idx += 256) {
        int o = idx >> 6, k = idx & 63;
        const float* src = (o < 64) ? Wq : ((o < 128) ? Wk : Wv);
        sq[QW + o * 68 + k] = uaf(cvt_tf32(src[(o & 63) * 64 + k]));
    }
    if (tid < 192)
        sq[QB + tid] = (tid < 64) ? bq[tid] : ((tid < 128) ? bk[tid - 64] : bv[tid - 128]);

    auto issueX = [&](int j) {
        int p0  = (blockIdx.x * T_PER + j) * 128;
        int b   = p0 >> 16;
        int hw0 = p0 & 65535;
        const float* xb = x + (size_t)b * 64 * HWn + hw0;
        u32 dst = s2u(sq + QRAW + (j & 1) * 64 * XRS);
        #pragma unroll
        for (int i = 0; i < 8; i++) {
            int idx = tid + 256 * i;
            int ch = idx >> 5, seg = idx & 31;
            cpa16(dst + (u32)(ch * XRS + seg * 4) * 4, xb + (size_t)ch * HWn + seg * 4);
        }
    };

    issueX(0); CPA_COMMIT();

    for (int j = 0; j < T_PER; j++) {
        CPA_WAIT0();
        __syncthreads();
        if (j + 1 < T_PER) { issueX(j + 1); CPA_COMMIT(); }

        {
            const float* raw = sq + QRAW + (j & 1) * 64 * XRS;
            #pragma unroll
            for (int i = 0; i < 8; i++) {
                int idx = tid + 256 * i;
                int ch = idx >> 5, seg = idx & 31;
                float4 v = *(const float4*)(raw + ch * XRS + seg * 4);
                float4 h, l;
                h.x = uaf(cvt_tf32(v.x)); l.x = uaf(cvt_tf32(v.x - h.x));
                h.y = uaf(cvt_tf32(v.y)); l.y = uaf(cvt_tf32(v.y - h.y));
                h.z = uaf(cvt_tf32(v.z)); l.z = uaf(cvt_tf32(v.z - h.z));
                h.w = uaf(cvt_tf32(v.w)); l.w = uaf(cvt_tf32(v.w - h.w));
                *(float4*)(sq + QAH + ch * XRS + seg * 4) = h;
                *(float4*)(sq + QAL + ch * XRS + seg * 4) = l;
            }
        }
        __syncthreads();

        float acc[4][6][4];
        #pragma unroll
        for (int i = 0; i < 4; i++)
            #pragma unroll
            for (int jj = 0; jj < 6; jj++)
                #pragma unroll
                for (int q = 0; q < 4; q++) acc[i][jj][q] = 0.f;

        #pragma unroll
        for (int kk = 0; kk < 8; kk++) {
            const int kb = kk * 8;
            u32 ah[4][4], al[4][4];
            #pragma unroll
            for (int ms = 0; ms < 4; ms++) {
                int r = wm + ms * 16 + lr;
                const float* ph = sq + QAH + (kb + lc) * XRS + r;
                const float* pl = sq + QAL + (kb + lc) * XRS + r;
                ah[ms][0] = fau(ph[0]); ah[ms][1] = fau(ph[8]);
                ah[ms][2] = fau(ph[4 * XRS]); ah[ms][3] = fau(ph[4 * XRS + 8]);
                al[ms][0] = fau(pl[0]); al[ms][1] = fau(pl[8]);
                al[ms][2] = fau(pl[4 * XRS]); al[ms][3] = fau(pl[4 * XRS + 8]);
            }
            #pragma unroll
            for (int ns = 0; ns < 6; ns++) {
                const float* wp = sq + QW + (wn + ns * 8 + lr) * 68 + kb + lc;
                u32 b0 = fau(wp[0]), b1 = fau(wp[4]);
                #pragma unroll
                for (int ms = 0; ms < 4; ms++) {
                    mma8(acc[ms][ns], ah[ms][0], ah[ms][1], ah[ms][2], ah[ms][3], b0, b1);
                    mma8(acc[ms][ns], al[ms][0], al[ms][1], al[ms][2], al[ms][3], b0, b1);
                }
            }
        }

        int p0  = (blockIdx.x * T_PER + j) * 128;
        int b   = p0 >> 16;
        int hw0 = p0 & 65535;
        #pragma unroll
        for (int ms = 0; ms < 4; ms++) {
            int r0 = wm + ms * 16 + lr;
            #pragma unroll
            for (int ns = 0; ns < 6; ns++) {
                int n0 = wn + ns * 8 + 2 * lc;
                #pragma unroll
                for (int q = 0; q < 4; q++) {
                    int o = n0 + (q & 1);
                    int r = r0 + (q >> 1) * 8;
                    float v = acc[ms][ns][q] + sq[QB + o];
                    int proj = o >> 6;
                    if (proj == 0) v *= 0.25f;
                    g_qkv[((size_t)proj * NBC + (size_t)(b * 64 + (o & 63))) * HWn + hw0 + r]
                        = uaf(cvt_tf32(v));
                }
            }
        }
    }
}

// ---------------------------------------------------------------------------
// Kernel 2: attention, 256 threads (8 warps as 2m x 4n, warp tile 64x64).
// Phase A chunk=64, kk fully unrolled (cross-k software pipelining enabled);
// Phase C reads V natural layout, 8 chunks of 32.
// ---------------------------------------------------------------------------
#define PS_STRIDE 260
#define A64S 68
#define A64_BUF (384 * A64S)                 // 26112 floats per buffer
#define VS_STRIDE 260
#define VB_FLOATS (32 * VS_STRIDE)           // 8320 per buffer
#define PS_FLOATS  (128 * PS_STRIDE)         // 33280
#define OFF_VS     PS_FLOATS                 // V bufs [33280, 49920)
#define OFF_RED    (2 * A64_BUF)             // 52224 (beyond A-buffer span)
#define OFF_ROWSC  (OFF_RED + 512)
#define SMEM_ATTN_FLOATS (OFF_ROWSC + 128)   // 52864 -> 211,456 B

__global__ __launch_bounds__(256, 1)
void attn_kernel(const float* __restrict__ gamma, const float* __restrict__ beta,
                 const float* __restrict__ rmean, const float* __restrict__ rvar,
                 const float* __restrict__ alphap, float* __restrict__ out)
{
    extern __shared__ float sm[];
    float* Ps    = sm;                      // 128 x 260 (aliases A-buffer 0)
    float* Vs    = sm + OFF_VS;             // 2 x 32 x 260 (aliases A-buffer 1)
    float* reds  = sm + OFF_RED;
    float* rowsc = sm + OFF_ROWSC;

    const int tid  = threadIdx.x;
    const int lane = tid & 31;
    const int wid  = tid >> 5;
    const int wm   = (wid & 1) * 64;
    const int wn   = (wid >> 1) * 64;
    const int lr   = lane >> 2;
    const int lc   = lane & 3;

    const int bc = blockIdx.x >> 1;
    const int h0 = (blockIdx.x & 1) * 128;
    const int c  = bc & 63;

    const float* Qg = g_qkv + (size_t)bc * HWn + (size_t)h0 * 256;
    const float* Kg = g_qkv + (size_t)(NBC + bc) * HWn;
    const float* Vg = g_qkv + (size_t)(2 * NBC + bc) * HWn;

    float acc[4][8][4];
    #pragma unroll
    for (int i = 0; i < 4; i++)
        #pragma unroll
        for (int j = 0; j < 8; j++)
            #pragma unroll
            for (int k = 0; k < 4; k++) acc[i][j][k] = 0.f;

    // ===== Phase A: S = Q . K^T, k=256 in 4 cp.async-pipelined chunks of 64 =
    auto issueA = [&](int kc) {
        u32 d = s2u(sm + (kc & 1) * A64_BUF);
        const float* sq2 = Qg + kc * 64;
        const float* sk2 = Kg + kc * 64;
        #pragma unroll
        for (int i = 0; i < 24; i++) {
            int idx = tid + 256 * i;
            if (idx < 2048) {                       // Q: 128 rows x 16 float4
                int r = idx >> 4, seg = idx & 15;
                cpa16(d + (u32)(r * A64S + seg * 4) * 4, sq2 + (size_t)r * 256 + seg * 4);
            } else {                                // K: 256 rows x 16 float4
                int i2 = idx - 2048;
                int r = i2 >> 4, seg = i2 & 15;
                cpa16(d + (u32)(128 * A64S + r * A64S + seg * 4) * 4,
                      sk2 + (size_t)r * 256 + seg * 4);
            }
        }
    };
    // Phase C V chunk issue: 32 g-rows x 256 w, natural layout, stride 260
    auto issueV = [&](int gc) {
        u32 d = s2u(Vs + (gc & 1) * VB_FLOATS);
        const float* sv = Vg + (size_t)gc * 32 * 256;
        #pragma unroll
        for (int i = 0; i < 8; i++) {
            int idx = tid + 256 * i;
            int r = idx >> 6, seg = idx & 63;
            cpa16(d + (u32)(r * VS_STRIDE + seg * 4) * 4, sv + (size_t)r * 256 + seg * 4);
        }
    };

    issueA(0); CPA_COMMIT();
    for (int kc = 0; kc < 4; kc++) {
        CPA_WAIT0();
        __syncthreads();
        if (kc + 1 < 4) { issueA(kc + 1); CPA_COMMIT(); }
        const float* bufQ = sm + (kc & 1) * A64_BUF;
        const float* bufK = bufQ + 128 * A64S;
        #pragma unroll
        for (int kk = 0; kk < 8; kk++) {
            const int kb = kk * 8;
            u32 af[4][4];
            #pragma unroll
            for (int ms = 0; ms < 4; ms++) {
                const float* q = bufQ + (wm + ms * 16 + lr) * A64S + kb + lc;
                af[ms][0] = fau(q[0]);
                af[ms][1] = fau(q[8 * A64S]);
                af[ms][2] = fau(q[4]);
                af[ms][3] = fau(q[8 * A64S + 4]);
            }
            #pragma unroll
            for (int ns = 0; ns < 8; ns++) {
                const float* kp = bufK + (wn + ns * 8 + lr) * A64S + kb + lc;
                u32 b0 = fau(kp[0]);
                u32 b1 = fau(kp[4]);
                #pragma unroll
                for (int ms = 0; ms < 4; ms++)
                    mma8(acc[ms][ns], af[ms][0], af[ms][1], af[ms][2], af[ms][3], b0, b1);
            }
        }
    }

    // All Phase A buffer reads complete before V cp.asyncs land in the
    // aliased buffer-1 region and before Ps overwrites buffer 0.
    __syncthreads();
    issueV(0); CPA_COMMIT();

    // ===== Phase B: softmax over n (no max-sub; |S| <~ 8) ==================
    #pragma unroll
    for (int ms = 0; ms < 4; ms++)
        #pragma unroll
        for (int half = 0; half < 2; half++) {
            int row = wm + ms * 16 + lr + half * 8;
            float s = 0.f;
            #pragma unroll
            for (int ns = 0; ns < 8; ns++) {
                float e0 = __expf(acc[ms][ns][half * 2]);
                float e1 = __expf(acc[ms][ns][half * 2 + 1]);
                s += e0 + e1;
                *(float2*)(Ps + row * PS_STRIDE + wn + ns * 8 + 2 * lc) =
                    make_float2(uaf(cvt_tf32(e0)), uaf(cvt_tf32(e1)));
            }
            s += __shfl_xor_sync(0xffffffffu, s, 1);
            s += __shfl_xor_sync(0xffffffffu, s, 2);
            if (lc == 0) reds[row * 4 + (wid >> 1)] = s;
        }
    __syncthreads();
    if (tid < 128)
        rowsc[tid] = 1.f / (reds[tid * 4] + reds[tid * 4 + 1] + reds[tid * 4 + 2] + reds[tid * 4 + 3]);

    // ===== Phase C: out = P . V, k=256 g in 8 pipelined chunks of 32 =======
    #pragma unroll
    for (int i = 0; i < 4; i++)
        #pragma unroll
        for (int j = 0; j < 8; j++)
            #pragma unroll
            for (int k = 0; k < 4; k++) acc[i][j][k] = 0.f;

    for (int gc = 0; gc < 8; gc++) {
        CPA_WAIT0();
        __syncthreads();
        if (gc + 1 < 8) { issueV(gc + 1); CPA_COMMIT(); }
        const float* bufV = Vs + (gc & 1) * VB_FLOATS;
        #pragma unroll
        for (int kk = 0; kk < 4; kk++) {
            const int kb = kk * 8;
            u32 af[4][4];
            #pragma unroll
            for (int ms = 0; ms < 4; ms++) {
                const float* p = Ps + (wm + ms * 16 + lr) * PS_STRIDE + gc * 32 + kb + lc;
                af[ms][0] = fau(p[0]);
                af[ms][1] = fau(p[8 * PS_STRIDE]);
                af[ms][2] = fau(p[4]);
                af[ms][3] = fau(p[8 * PS_STRIDE + 4]);
            }
            #pragma unroll
            for (int ns = 0; ns < 8; ns++) {
                // B fragment straight from natural V: VT[n][k] == Vs[k][n]
                const float* vb = bufV + (kb + lc) * VS_STRIDE + wn + ns * 8 + lr;
                u32 b0 = fau(vb[0]);
                u32 b1 = fau(vb[4 * VS_STRIDE]);
                #pragma unroll
                for (int ms = 0; ms < 4; ms++)
                    mma8(acc[ms][ns], af[ms][0], af[ms][1], af[ms][2], af[ms][3], b0, b1);
            }
        }
    }

    // ===== Epilogue: 1/sum, BN(eval), PReLU, store =========================
    const float inv = gamma[c] * rsqrtf(rvar[c] + 1e-5f);
    const float sh  = beta[c] - rmean[c] * inv;
    const float al  = alphap[0];
    #pragma unroll
    for (int ms = 0; ms < 4; ms++)
        #pragma unroll
        for (int half = 0; half < 2; half++) {
            int row = wm + ms * 16 + lr + half * 8;
            float rs = rowsc[row] * inv;
            float* op = out + (size_t)bc * HWn + (size_t)(h0 + row) * 256;
            #pragma unroll
            for (int ns = 0; ns < 8; ns++) {
                float v0 = acc[ms][ns][half * 2]     * rs + sh;
                float v1 = acc[ms][ns][half * 2 + 1] * rs + sh;
                v0 = (v0 >= 0.f) ? v0 : al * v0;
                v1 = (v1 >= 0.f) ? v1 : al * v1;
                *(float2*)(op + wn + ns * 8 + 2 * lc) = make_float2(v0, v1);
            }
        }
}

// ---------------------------------------------------------------------------
extern "C" void kernel_launch(void* const* d_in, const int* in_sizes, int n_in,
                              void* d_out, int out_size)
{
    (void)in_sizes; (void)n_in; (void)out_size;
    const float* x     = (const float*)d_in[0];
    const float* Wq    = (const float*)d_in[1];
    const float* bq    = (const float*)d_in[2];
    const float* Wk    = (const float*)d_in[3];
    const float* bk    = (const float*)d_in[4];
    const float* Wv    = (const float*)d_in[5];
    const float* bv    = (const float*)d_in[6];
    const float* gamma = (const float*)d_in[7];
    const float* beta  = (const float*)d_in[8];
    const float* rmean = (const float*)d_in[9];
    const float* rvar  = (const float*)d_in[10];
    const float* alpha = (const float*)d_in[11];
    float* out = (float*)d_out;

    const int smem1 = SMEM_QKV_FLOATS * sizeof(float);    // 192,256 B
    const int smem2 = SMEM_ATTN_FLOATS * sizeof(float);   // 211,456 B
    cudaFuncSetAttribute(qkv_mma,     cudaFuncAttributeMaxDynamicSharedMemorySize, smem1);
    cudaFuncSetAttribute(attn_kernel, cudaFuncAttributeMaxDynamicSharedMemorySize, smem2);

    qkv_mma<<<1024, 256, smem1>>>(x, Wq, bq, Wk, bk, Wv, bv);
    attn_kernel<<<NBC * 2, 256, smem2>>>(gamma, beta, rmean, rvar, alpha, out);
}

// round 15
// speedup vs baseline: 1.1988x; 1.1319x over previous
#include <cuda_runtime.h>
#include <math.h>

typedef unsigned int u32;
typedef unsigned long long u64;

#define HWn 65536
#define NBC 512

// Q,K,V scratch (fp32, tf32-prerounded), layout [proj][b*64+c][h*256+w]
__device__ float g_qkv[3ULL * NBC * HWn];

// ---------------- helpers ---------------------------------------------------
__device__ __forceinline__ u32 s2u(const void* p) { return (u32)__cvta_generic_to_shared(p); }
__device__ __forceinline__ u32 cvt_tf32(float f) {
    u32 r; asm("cvt.rna.tf32.f32 %0,%1;" : "=r"(r) : "f"(f)); return r;
}
__device__ __forceinline__ u32 fau(float f) { return __float_as_uint(f); }
__device__ __forceinline__ float uaf(u32 u) { return __uint_as_float(u); }
__device__ __forceinline__ void mma8(float* c, u32 a0, u32 a1, u32 a2, u32 a3,
                                     u32 b0, u32 b1) {
    asm("mma.sync.aligned.m16n8k8.row.col.f32.tf32.tf32.f32 "
        "{%0,%1,%2,%3},{%4,%5,%6,%7},{%8,%9},{%0,%1,%2,%3};"
        : "+f"(c[0]), "+f"(c[1]), "+f"(c[2]), "+f"(c[3])
        : "r"(a0), "r"(a1), "r"(a2), "r"(a3), "r"(b0), "r"(b1));
}
__device__ __forceinline__ void cpa16(u32 smem, const float* g) {
    asm volatile("cp.async.cg.shared.global [%0],[%1],16;" :: "r"(smem), "l"(g));
}
#define CPA_COMMIT() asm volatile("cp.async.commit_group;" ::: "memory")
#define CPA_WAIT0()  asm volatile("cp.async.wait_group 0;" ::: "memory")

// ---------------------------------------------------------------------------
// Kernel 1: QKV projection, persistent CTAs. Single-term tf32 MMA (x rounded
// to tf32; the output is tf32-rounded for the attention stage anyway).
// ---------------------------------------------------------------------------
#define T_PER 4
#define XRS 136
#define QW   0
#define QB   (192*68)
#define QAH  (QB + 192)
#define QRAW (QAH + 64*XRS)
#define SMEM_QKV_FLOATS (QRAW + 2*64*XRS)     // 39360 -> 157,440 B

__global__ __launch_bounds__(256, 1)
void qkv_mma(const float* __restrict__ x,
             const float* __restrict__ Wq, const float* __restrict__ bq,
             const float* __restrict__ Wk, const float* __restrict__ bk,
             const float* __restrict__ Wv, const float* __restrict__ bv)
{
    extern __shared__ float sq[];
    const int tid  = threadIdx.x;
    const int lane = tid & 31;
    const int wid  = tid >> 5;
    const int lr   = lane >> 2;
    const int lc   = lane & 3;
    const int wm   = (wid & 1) * 64;
    const int wn   = (wid >> 1) * 48;

    for (int idx = tid; idx < 192 * 64; idx += 256) {
        int o = idx >> 6, k = idx & 63;
        const float* src = (o < 64) ? Wq : ((o < 128) ? Wk : Wv);
        sq[QW + o * 68 + k] = uaf(cvt_tf32(src[(o & 63) * 64 + k]));
    }
    if (tid < 192)
        sq[QB + tid] = (tid < 64) ? bq[tid] : ((tid < 128) ? bk[tid - 64] : bv[tid - 128]);

    auto issueX = [&](int j) {
        int p0  = (blockIdx.x * T_PER + j) * 128;
        int b   = p0 >> 16;
        int hw0 = p0 & 65535;
        const float* xb = x + (size_t)b * 64 * HWn + hw0;
        u32 dst = s2u(sq + QRAW + (j & 1) * 64 * XRS);
        #pragma unroll
        for (int i = 0; i < 8; i++) {
            int idx = tid + 256 * i;
            int ch = idx >> 5, seg = idx & 31;
            cpa16(dst + (u32)(ch * XRS + seg * 4) * 4, xb + (size_t)ch * HWn + seg * 4);
        }
    };

    issueX(0); CPA_COMMIT();

    for (int j = 0; j < T_PER; j++) {
        CPA_WAIT0();
        __syncthreads();
        if (j + 1 < T_PER) { issueX(j + 1); CPA_COMMIT(); }

        {   // round pass: raw -> Ah (tf32)
            const float* raw = sq + QRAW + (j & 1) * 64 * XRS;
            #pragma unroll
            for (int i = 0; i < 8; i++) {
                int idx = tid + 256 * i;
                int ch = idx >> 5, seg = idx & 31;
                float4 v = *(const float4*)(raw + ch * XRS + seg * 4);
                float4 h;
                h.x = uaf(cvt_tf32(v.x));
                h.y = uaf(cvt_tf32(v.y));
                h.z = uaf(cvt_tf32(v.z));
                h.w = uaf(cvt_tf32(v.w));
                *(float4*)(sq + QAH + ch * XRS + seg * 4) = h;
            }
        }
        __syncthreads();

        float acc[4][6][4];
        #pragma unroll
        for (int i = 0; i < 4; i++)
            #pragma unroll
            for (int jj = 0; jj < 6; jj++)
                #pragma unroll
                for (int q = 0; q < 4; q++) acc[i][jj][q] = 0.f;

        #pragma unroll
        for (int kk = 0; kk < 8; kk++) {
            const int kb = kk * 8;
            u32 ah[4][4];
            #pragma unroll
            for (int ms = 0; ms < 4; ms++) {
                int r = wm + ms * 16 + lr;
                const float* ph = sq + QAH + (kb + lc) * XRS + r;
                ah[ms][0] = fau(ph[0]); ah[ms][1] = fau(ph[8]);
                ah[ms][2] = fau(ph[4 * XRS]); ah[ms][3] = fau(ph[4 * XRS + 8]);
            }
            #pragma unroll
            for (int ns = 0; ns < 6; ns++) {
                const float* wp = sq + QW + (wn + ns * 8 + lr) * 68 + kb + lc;
                u32 b0 = fau(wp[0]), b1 = fau(wp[4]);
                #pragma unroll
                for (int ms = 0; ms < 4; ms++)
                    mma8(acc[ms][ns], ah[ms][0], ah[ms][1], ah[ms][2], ah[ms][3], b0, b1);
            }
        }

        int p0  = (blockIdx.x * T_PER + j) * 128;
        int b   = p0 >> 16;
        int hw0 = p0 & 65535;
        #pragma unroll
        for (int ms = 0; ms < 4; ms++) {
            int r0 = wm + ms * 16 + lr;
            #pragma unroll
            for (int ns = 0; ns < 6; ns++) {
                int n0 = wn + ns * 8 + 2 * lc;
                #pragma unroll
                for (int q = 0; q < 4; q++) {
                    int o = n0 + (q & 1);
                    int r = r0 + (q >> 1) * 8;
                    float v = acc[ms][ns][q] + sq[QB + o];
                    int proj = o >> 6;
                    if (proj == 0) v *= 0.25f;
                    g_qkv[((size_t)proj * NBC + (size_t)(b * 64 + (o & 63))) * HWn + hw0 + r]
                        = uaf(cvt_tf32(v));
                }
            }
        }
    }
}

// ---------------------------------------------------------------------------
// Kernel 2: attention (byte-identical to round 13/14 best config).
// ---------------------------------------------------------------------------
#define PS_STRIDE 260
#define A64S 68
#define A64_BUF (384 * A64S)                 // 26112 floats per buffer
#define VS_STRIDE 260
#define VB_FLOATS (32 * VS_STRIDE)           // 8320 per buffer
#define PS_FLOATS  (128 * PS_STRIDE)         // 33280
#define OFF_VS     PS_FLOATS                 // V bufs [33280, 49920)
#define OFF_RED    (2 * A64_BUF)             // 52224 (beyond A-buffer span)
#define OFF_ROWSC  (OFF_RED + 512)
#define SMEM_ATTN_FLOATS (OFF_ROWSC + 128)   // 52864 -> 211,456 B

__global__ __launch_bounds__(256, 1)
void attn_kernel(const float* __restrict__ gamma, const float* __restrict__ beta,
                 const float* __restrict__ rmean, const float* __restrict__ rvar,
                 const float* __restrict__ alphap, float* __restrict__ out)
{
    extern __shared__ float sm[];
    float* Ps    = sm;                      // 128 x 260 (aliases A-buffer 0)
    float* Vs    = sm + OFF_VS;             // 2 x 32 x 260 (aliases A-buffer 1)
    float* reds  = sm + OFF_RED;
    float* rowsc = sm + OFF_ROWSC;

    const int tid  = threadIdx.x;
    const int lane = tid & 31;
    const int wid  = tid >> 5;
    const int wm   = (wid & 1) * 64;
    const int wn   = (wid >> 1) * 64;
    const int lr   = lane >> 2;
    const int lc   = lane & 3;

    const int bc = blockIdx.x >> 1;
    const int h0 = (blockIdx.x & 1) * 128;
    const int c  = bc & 63;

    const float* Qg = g_qkv + (size_t)bc * HWn + (size_t)h0 * 256;
    const float* Kg = g_qkv + (size_t)(NBC + bc) * HWn;
    const float* Vg = g_qkv + (size_t)(2 * NBC + bc) * HWn;

    float acc[4][8][4];
    #pragma unroll
    for (int i = 0; i < 4; i++)
        #pragma unroll
        for (int j = 0; j < 8; j++)
            #pragma unroll
            for (int k = 0; k < 4; k++) acc[i][j][k] = 0.f;

    // ===== Phase A: S = Q . K^T, k=256 in 4 cp.async-pipelined chunks of 64 =
    auto issueA = [&](int kc) {
        u32 d = s2u(sm + (kc & 1) * A64_BUF);
        const float* sq2 = Qg + kc * 64;
        const float* sk2 = Kg + kc * 64;
        #pragma unroll
        for (int i = 0; i < 24; i++) {
            int idx = tid + 256 * i;
            if (idx < 2048) {                       // Q: 128 rows x 16 float4
                int r = idx >> 4, seg = idx & 15;
                cpa16(d + (u32)(r * A64S + seg * 4) * 4, sq2 + (size_t)r * 256 + seg * 4);
            } else {                                // K: 256 rows x 16 float4
                int i2 = idx - 2048;
                int r = i2 >> 4, seg = i2 & 15;
                cpa16(d + (u32)(128 * A64S + r * A64S + seg * 4) * 4,
                      sk2 + (size_t)r * 256 + seg * 4);
            }
        }
    };
    // Phase C V chunk issue: 32 g-rows x 256 w, natural layout, stride 260
    auto issueV = [&](int gc) {
        u32 d = s2u(Vs + (gc & 1) * VB_FLOATS);
        const float* sv = Vg + (size_t)gc * 32 * 256;
        #pragma unroll
        for (int i = 0; i < 8; i++) {
            int idx = tid + 256 * i;
            int r = idx >> 6, seg = idx & 63;
            cpa16(d + (u32)(r * VS_STRIDE + seg * 4) * 4, sv + (size_t)r * 256 + seg * 4);
        }
    };

    issueA(0); CPA_COMMIT();
    for (int kc = 0; kc < 4; kc++) {
        CPA_WAIT0();
        __syncthreads();
        if (kc + 1 < 4) { issueA(kc + 1); CPA_COMMIT(); }
        const float* bufQ = sm + (kc & 1) * A64_BUF;
        const float* bufK = bufQ + 128 * A64S;
        #pragma unroll
        for (int kk = 0; kk < 8; kk++) {
            const int kb = kk * 8;
            u32 af[4][4];
            #pragma unroll
            for (int ms = 0; ms < 4; ms++) {
                const float* q = bufQ + (wm + ms * 16 + lr) * A64S + kb + lc;
                af[ms][0] = fau(q[0]);
                af[ms][1] = fau(q[8 * A64S]);
                af[ms][2] = fau(q[4]);
                af[ms][3] = fau(q[8 * A64S + 4]);
            }
            #pragma unroll
            for (int ns = 0; ns < 8; ns++) {
                const float* kp = bufK + (wn + ns * 8 + lr) * A64S + kb + lc;
                u32 b0 = fau(kp[0]);
                u32 b1 = fau(kp[4]);
                #pragma unroll
                for (int ms = 0; ms < 4; ms++)
                    mma8(acc[ms][ns], af[ms][0], af[ms][1], af[ms][2], af[ms][3], b0, b1);
            }
        }
    }

    // All Phase A buffer reads complete before V cp.asyncs land in the
    // aliased buffer-1 region and before Ps overwrites buffer 0.
    __syncthreads();
    issueV(0); CPA_COMMIT();

    // ===== Phase B: softmax over n (no max-sub; |S| <~ 8) ==================
    #pragma unroll
    for (int ms = 0; ms < 4; ms++)
        #pragma unroll
        for (int half = 0; half < 2; half++) {
            int row = wm + ms * 16 + lr + half * 8;
            float s = 0.f;
            #pragma unroll
            for (int ns = 0; ns < 8; ns++) {
                float e0 = __expf(acc[ms][ns][half * 2]);
                float e1 = __expf(acc[ms][ns][half * 2 + 1]);
                s += e0 + e1;
                *(float2*)(Ps + row * PS_STRIDE + wn + ns * 8 + 2 * lc) =
                    make_float2(uaf(cvt_tf32(e0)), uaf(cvt_tf32(e1)));
            }
            s += __shfl_xor_sync(0xffffffffu, s, 1);
            s += __shfl_xor_sync(0xffffffffu, s, 2);
            if (lc == 0) reds[row * 4 + (wid >> 1)] = s;
        }
    __syncthreads();
    if (tid < 128)
        rowsc[tid] = 1.f / (reds[tid * 4] + reds[tid * 4 + 1] + reds[tid * 4 + 2] + reds[tid * 4 + 3]);

    // ===== Phase C: out = P . V, k=256 g in 8 pipelined chunks of 32 =======
    #pragma unroll
    for (int i = 0; i < 4; i++)
        #pragma unroll
        for (int j = 0; j < 8; j++)
            #pragma unroll
            for (int k = 0; k < 4; k++) acc[i][j][k] = 0.f;

    for (int gc = 0; gc < 8; gc++) {
        CPA_WAIT0();
        __syncthreads();
        if (gc + 1 < 8) { issueV(gc + 1); CPA_COMMIT(); }
        const float* bufV = Vs + (gc & 1) * VB_FLOATS;
        #pragma unroll
        for (int kk = 0; kk < 4; kk++) {
            const int kb = kk * 8;
            u32 af[4][4];
            #pragma unroll
            for (int ms = 0; ms < 4; ms++) {
                const float* p = Ps + (wm + ms * 16 + lr) * PS_STRIDE + gc * 32 + kb + lc;
                af[ms][0] = fau(p[0]);
                af[ms][1] = fau(p[8 * PS_STRIDE]);
                af[ms][2] = fau(p[4]);
                af[ms][3] = fau(p[8 * PS_STRIDE + 4]);
            }
            #pragma unroll
            for (int ns = 0; ns < 8; ns++) {
                // B fragment straight from natural V: VT[n][k] == Vs[k][n]
                const float* vb = bufV + (kb + lc) * VS_STRIDE + wn + ns * 8 + lr;
                u32 b0 = fau(vb[0]);
                u32 b1 = fau(vb[4 * VS_STRIDE]);
                #pragma unroll
                for (int ms = 0; ms < 4; ms++)
                    mma8(acc[ms][ns], af[ms][0], af[ms][1], af[ms][2], af[ms][3], b0, b1);
            }
        }
    }

    // ===== Epilogue: 1/sum, BN(eval), PReLU, store =========================
    const float inv = gamma[c] * rsqrtf(rvar[c] + 1e-5f);
    const float sh  = beta[c] - rmean[c] * inv;
    const float al  = alphap[0];
    #pragma unroll
    for (int ms = 0; ms < 4; ms++)
        #pragma unroll
        for (int half = 0; half < 2; half++) {
            int row = wm + ms * 16 + lr + half * 8;
            float rs = rowsc[row] * inv;
            float* op = out + (size_t)bc * HWn + (size_t)(h0 + row) * 256;
            #pragma unroll
            for (int ns = 0; ns < 8; ns++) {
                float v0 = acc[ms][ns][half * 2]     * rs + sh;
                float v1 = acc[ms][ns][half * 2 + 1] * rs + sh;
                v0 = (v0 >= 0.f) ? v0 : al * v0;
                v1 = (v1 >= 0.f) ? v1 : al * v1;
                *(float2*)(op + wn + ns * 8 + 2 * lc) = make_float2(v0, v1);
            }
        }
}

// ---------------------------------------------------------------------------
extern "C" void kernel_launch(void* const* d_in, const int* in_sizes, int n_in,
                              void* d_out, int out_size)
{
    (void)in_sizes; (void)n_in; (void)out_size;
    const float* x     = (const float*)d_in[0];
    const float* Wq    = (const float*)d_in[1];
    const float* bq    = (const float*)d_in[2];
    const float* Wk    = (const float*)d_in[3];
    const float* bk    = (const float*)d_in[4];
    const float* Wv    = (const float*)d_in[5];
    const float* bv    = (const float*)d_in[6];
    const float* gamma = (const float*)d_in[7];
    const float* beta  = (const float*)d_in[8];
    const float* rmean = (const float*)d_in[9];
    const float* rvar  = (const float*)d_in[10];
    const float* alpha = (const float*)d_in[11];
    float* out = (float*)d_out;

    const int smem1 = SMEM_QKV_FLOATS * sizeof(float);    // 157,440 B
    const int smem2 = SMEM_ATTN_FLOATS * sizeof(float);   // 211,456 B
    cudaFuncSetAttribute(qkv_mma,     cudaFuncAttributeMaxDynamicSharedMemorySize, smem1);
    cudaFuncSetAttribute(attn_kernel, cudaFuncAttributeMaxDynamicSharedMemorySize, smem2);

    qkv_mma<<<1024, 256, smem1>>>(x, Wq, bq, Wk, bk, Wv, bv);
    attn_kernel<<<NBC * 2, 256, smem2>>>(gamma, beta, rmean, rvar, alpha, out);
}